// round 12
// baseline (speedup 1.0000x reference)
#include <cuda_runtime.h>
#include <cuda_bf16.h>

// MultiTaskLoss: B=64 samples, 512x512, scalar loss output.
// R12: ONE fused kernel. Bids [0,4160) build row bitmasks + horizontal d^2
//      (per-sample producers, 65 blocks/sample incl. 1 pad block);
//      bids [4160,8256) are main-loss consumers that spin on a per-sample
//      counter (deadlock-free: consumers only wait on lower-bid blocks).
//      Finalize block resets all counters/accumulators for graph replays.

#define BN 64
#define HH 512
#define WW 512
#define NPIX (HH * WW)
#define PROWS (HH + 20)            // 10 pad rows top/bottom
#define MASK_BPS 65                // maskdxh blocks per sample
#define MAIN_BPS 64                // main blocks per sample
#define MASK_TOTAL (BN * MASK_BPS) // 4160
#define MAIN_TOTAL (BN * MAIN_BPS) // 4096
#define TOTAL_BLOCKS (MASK_TOTAL + MAIN_TOTAL)

__device__ unsigned long long g_dxh[BN * PROWS * WW / 8];   // horiz d^2, u8x8
__device__ float              g_acc[BN * 8];                // reset by finalize
__device__ unsigned           g_cnt[BN];                    // reset by finalize
__device__ unsigned           g_done;                       // reset by finalize

// ---------------------------------------------------------------------------
// nearest-set-bit distance^2 (clamped 101) from center (bit 10) of 21-bit window
__device__ __forceinline__ int win_d2(unsigned win) {
    unsigned lo = win & 0x7FFu;            // bits 0..10 (left side, center incl)
    unsigned hi = win >> 10;               // bits 0..10 (right side, center incl)
    int dl = __clz(lo) - 21;               // lo==0 -> 11 (no guard needed)
    int dh = __clz(__brev(hi));            // lowest set bit idx; hi==0 -> 32
    int d  = min(min(dl, dh), 11);
    return min(d * d, 101);
}

// ---------------------------------------------------------------------------
__global__ void __launch_bounds__(256, 6) fused_kernel(
    const float4* __restrict__ preds4,
    const float4* __restrict__ targets4,
    const int*    __restrict__ task_ids,
    float*        __restrict__ out)
{
    int bid = blockIdx.x;
    int t   = threadIdx.x;

    // ======================= PRODUCER ROLE =======================
    if (bid < MASK_TOTAL) {
        int b = bid / MASK_BPS;
        int s = bid - b * MASK_BPS;

        if (s == 64) {
            // pad rows: 20 rows * 64 u64 words = 101 per byte
            for (int i = t; i < 20 * 64; i += 256) {
                int r = i >> 6;
                int row = (r < 10) ? r : r + 512;   // 0..9 and 522..531
                g_dxh[(b * PROWS + row) * 64 + (i & 63)] = 0x6565656565656565ull;
            }
        } else {
            __shared__ unsigned smask[8][18];   // 8 rows, 16+2 pad words
            int y0 = s * 8;

            if (t < 144) ((unsigned*)smask)[t] = 0u;
            __syncthreads();

            // build masks: 16 px/thread, lane-pair REDUX.OR -> one word / 32 px
            int g4 = ((b * NPIX + y0 * WW) >> 2) + t * 4;
            float4 v0 = targets4[g4 + 0];
            float4 v1 = targets4[g4 + 1];
            float4 v2 = targets4[g4 + 2];
            float4 v3 = targets4[g4 + 3];
            unsigned m =
                  (v0.x > 0.5f ? 0x0001u : 0u) | (v0.y > 0.5f ? 0x0002u : 0u)
                | (v0.z > 0.5f ? 0x0004u : 0u) | (v0.w > 0.5f ? 0x0008u : 0u)
                | (v1.x > 0.5f ? 0x0010u : 0u) | (v1.y > 0.5f ? 0x0020u : 0u)
                | (v1.z > 0.5f ? 0x0040u : 0u) | (v1.w > 0.5f ? 0x0080u : 0u)
                | (v2.x > 0.5f ? 0x0100u : 0u) | (v2.y > 0.5f ? 0x0200u : 0u)
                | (v2.z > 0.5f ? 0x0400u : 0u) | (v2.w > 0.5f ? 0x0800u : 0u)
                | (v3.x > 0.5f ? 0x1000u : 0u) | (v3.y > 0.5f ? 0x2000u : 0u)
                | (v3.z > 0.5f ? 0x4000u : 0u) | (v3.w > 0.5f ? 0x8000u : 0u);

            unsigned lane  = t & 31;
            unsigned gmask = 0x3u << (lane & ~1u);       // lane pair = 32 px
            unsigned word  = __reduce_or_sync(gmask, m << ((lane & 1) * 16));
            if ((lane & 1) == 0) {
                int p0 = t * 16;
                smask[p0 >> 9][1 + ((p0 & 511) >> 5)] = word;
            }
            __syncthreads();

            // horizontal d^2: 16 px/thread (2 u64 outputs)
            int r  = t >> 5;
            int x0 = (t & 31) << 4;
            const unsigned* rowp = &smask[r][0];
            unsigned long long ob =
                (unsigned long long)(b * PROWS + 10 + y0 + r) * 64;
            #pragma unroll
            for (int k = 0; k < 2; ++k) {
                int sx = x0 + k * 8 - 10;
                const unsigned* rp = rowp + 1 + (sx >> 5);
                unsigned long long w =
                    (((unsigned long long)rp[1] << 32) | rp[0]) >> (sx & 31);
                unsigned long long o = 0ull;
                #pragma unroll
                for (int j = 0; j < 8; ++j) {
                    unsigned win = (unsigned)(w >> j) & 0x1FFFFFu;
                    o |= (unsigned long long)win_d2(win) << (8 * j);
                }
                g_dxh[ob + (x0 >> 3) + k] = o;
            }
        }

        // signal: this sample-b producer block is done
        __threadfence();
        __syncthreads();
        if (t == 0) atomicAdd(&g_cnt[b], 1u);
        return;
    }

    // ======================= CONSUMER ROLE =======================
    int mb  = bid - MASK_TOTAL;
    int b   = mb >> 6;                      // sample
    int si  = (mb & 63) * 256 + t;          // 16-px strip index in sample
    int y   = si >> 5;
    int xo  = si & 31;
    int q   = b * (NPIX / 16) + si;

    __shared__ float sTab[102];
    if (t < 102) sTab[t] = fminf(sqrtf((float)t), 10.0f);

    // issue preds loads before the spin (independent of dxh)
    float4 xv[4];
    #pragma unroll
    for (int k = 0; k < 4; ++k) xv[k] = preds4[q * 4 + k];

    // wait for all 65 producer blocks of this sample
    if (t == 0) {
        while (atomicAdd(&g_cnt[b], 0u) < MASK_BPS) __nanosleep(64);
    }
    __syncthreads();
    __threadfence();   // order subsequent g_dxh reads after the counter load

    // ---- byte-SIMD vertical DT (128-bit loads) ----
    const ulonglong2* bp = (const ulonglong2*)g_dxh + (b * PROWS + 10 + y) * 32 + xo;
    ulonglong2 cur = *bp;
    unsigned bw[4] = {(unsigned)cur.x, (unsigned)(cur.x >> 32),
                      (unsigned)cur.y, (unsigned)(cur.y >> 32)};

    #pragma unroll 1
    for (int ady = 1; ady <= 10; ++ady) {
        int a2 = ady * ady;
        unsigned m4 = __vmaxu4(__vmaxu4(bw[0], bw[1]), __vmaxu4(bw[2], bw[3]));
        m4 = __vmaxu4(m4, m4 >> 16);
        m4 = __vmaxu4(m4, m4 >> 8);
        if (a2 >= (int)(m4 & 0xFFu)) break;
        ulonglong2 up = bp[-(ady * 32)];
        ulonglong2 dn = bp[  ady * 32 ];
        unsigned a2b = a2 * 0x01010101u;   // per-byte add, sums < 256: no carry
        bw[0] = __vminu4(bw[0], __vminu4((unsigned)up.x,         (unsigned)dn.x)         + a2b);
        bw[1] = __vminu4(bw[1], __vminu4((unsigned)(up.x >> 32), (unsigned)(dn.x >> 32)) + a2b);
        bw[2] = __vminu4(bw[2], __vminu4((unsigned)up.y,         (unsigned)dn.y)         + a2b);
        bw[3] = __vminu4(bw[3], __vminu4((unsigned)(up.y >> 32), (unsigned)(dn.y >> 32)) + a2b);
    }

    // ---- pointwise math + 6 sums over 16 px ----
    // byte==0 <=> fg. No clamps (preds ~ N(0,1)). s4 = sum dist*p.
    float s2 = (float)(__popc(__vseteq4(bw[0], 0u)) + __popc(__vseteq4(bw[1], 0u))
                     + __popc(__vseteq4(bw[2], 0u)) + __popc(__vseteq4(bw[3], 0u)));
    float s0 = 0.f, s1 = 0.f, s4 = 0.f, s5 = 0.f, s6 = 0.f;
    #pragma unroll
    for (int j = 0; j < 16; ++j) {
        float x_ = ((const float*)xv)[j];
        unsigned b2 = (bw[j >> 2] >> ((j & 3) * 8)) & 0xFFu;

        float ax = fabsf(x_);
        float e  = __expf(-ax);
        float pa = __fdividef(1.0f, 1.0f + e);    // sigmoid(|x|)
        float lp = __logf(pa);                    // = -log1p(e)
        // softplus(x) = max(x,0) - lp = 0.5x + 0.5|x| - lp (FMA, not FMNMX)
        float sp_pos = fmaf(0.5f, x_, fmaf(0.5f, ax, -lp));
        float sp_neg = sp_pos - x_;               // softplus(-x) = -log(p)
        float p  = (x_ >= 0.0f) ? pa : (1.0f - pa);

        s1 += p;
        s4 = fmaf(sTab[b2], p, s4);
        if (b2 == 0) {      // foreground
            s0 += p;
            s5 += sp_neg;
        } else {            // background
            s6 += sp_pos;
        }
    }

    // ---- block reduction: warp shuffle -> shared -> per-sample atomics ----
    float vals[6] = {s0, s1, s2, s4, s5, s6};
    __shared__ float shr[8 * 6];
    int lane = t & 31;
    int wid  = t >> 5;
    #pragma unroll
    for (int qq = 0; qq < 6; ++qq) {
        float v = vals[qq];
        #pragma unroll
        for (int o = 16; o; o >>= 1) v += __shfl_down_sync(0xffffffffu, v, o);
        if (lane == 0) shr[wid * 6 + qq] = v;
    }
    __syncthreads();
    if (t < 6) {
        float ssum = 0.0f;
        #pragma unroll
        for (int w = 0; w < 8; ++w) ssum += shr[w * 6 + t];
        atomicAdd(&g_acc[b * 8 + t], ssum);
    }

    // ---- last consumer block finalizes + resets state for next replay ----
    __shared__ unsigned sIsLast;
    __threadfence();
    __syncthreads();
    if (t == 0)
        sIsLast = (atomicAdd(&g_done, 1u) == MAIN_TOTAL - 1) ? 1u : 0u;
    __syncthreads();
    if (sIsLast) {
        __shared__ float shp[64];
        if (t < 64) {
            int bb = t;
            const float Nf   = (float)NPIX;
            const float invN = 1.0f / Nf;
            float* a = &g_acc[bb * 8];
            float Sint = a[0], Spc = a[1], St = a[2];
            float Sbd  = a[3], Sfg = a[4], Sbg = a[5];
            float Sbce = Sfg + Sbg;

            float dice = 1.0f - (2.0f * Sint + 1e-5f) / (Spc + St + 1e-5f);
            float base = dice + Sbce * invN;
            float boundary = Sbd * invN;
            float fgw = fminf(fmaxf((Nf - St) / (St + 1e-7f), 1.0f), 10.0f);
            float fgl = (St == 0.0f) ? 0.0f : (fgw * Sfg + Sbg) * invN;

            const float DW[3] = {2.0f, 3.0f, 5.0f};
            const float FW[3] = {1.0f, 1.5f, 3.0f};
            int ti = task_ids[bb];
            shp[bb] = base + DW[ti] * boundary + FW[ti] * fgl;  // BASE_W == 1
        }
        __syncthreads();
        if (t == 0) {
            float ssum = 0.0f;
            #pragma unroll
            for (int i = 0; i < 64; ++i) ssum += shp[i];
            out[0] = ssum * (1.0f / 64.0f);
            g_done = 0u;
        }
        // reset per-sample counters + accumulators for the next graph replay
        if (t < BN) g_cnt[t] = 0u;
        if (t < BN * 8 && t >= 0) { /* spread below */ }
        for (int i = t; i < BN * 8; i += 256) g_acc[i] = 0.0f;
    }
}

// ---------------------------------------------------------------------------
extern "C" void kernel_launch(void* const* d_in, const int* in_sizes, int n_in,
                              void* d_out, int out_size)
{
    const float* preds = (const float*)d_in[0];
    const float* targs = (const float*)d_in[1];
    const int*   tids  = (const int*)d_in[2];
    float*       out   = (float*)d_out;

    fused_kernel<<<TOTAL_BLOCKS, 256>>>((const float4*)preds,
                                        (const float4*)targs, tids, out);
}